// round 5
// baseline (speedup 1.0000x reference)
#include <cuda_runtime.h>
#include <math.h>
#include <stdint.h>

#define LSEQ  32768
#define CDIM  256      // projected channels
#define QDIM  512      // input/output channels
#define BLK   512      // attention block length
#define HALF  256
#define QT    64       // query tile per CTA

typedef unsigned long long u64;

// ---- packed f32x2 helpers (sm_100+; ptxas never auto-generates FFMA2) ----
__device__ __forceinline__ u64 pk2(float lo, float hi) {
    u64 r;
    asm("mov.b64 %0, {%1, %2};" : "=l"(r)
        : "r"(__float_as_uint(lo)), "r"(__float_as_uint(hi)));
    return r;
}
__device__ __forceinline__ u64 dup2(float v) { return pk2(v, v); }
__device__ __forceinline__ void fma2(u64 &d, u64 a, u64 b) {
    asm("fma.rn.f32x2 %0, %1, %2, %0;" : "+l"(d) : "l"(a), "l"(b));
}
__device__ __forceinline__ void mul2(u64 &d, u64 a) {
    asm("mul.rn.f32x2 %0, %0, %1;" : "+l"(d) : "l"(a));
}
__device__ __forceinline__ float2 up2(u64 v) {
    float2 f;
    unsigned lo, hi;
    asm("mov.b64 {%0, %1}, %2;" : "=r"(lo), "=r"(hi) : "l"(v));
    f.x = __uint_as_float(lo); f.y = __uint_as_float(hi);
    return f;
}

// ---- scratch (static device globals; runtime alloc is forbidden) ----
__device__ float g_q[(size_t)CDIM * LSEQ];
__device__ float g_k[(size_t)CDIM * LSEQ];
__device__ float g_v[(size_t)CDIM * LSEQ];
__device__ float g_att[(size_t)CDIM * LSEQ];

// ============================================================================
// GEMM: out[m][l] = bias[m] + sum_k W[m][k] * X[k][l]   (optionally * mm[l])
// X/out row stride LSEQ. Tile 128x128, BK=16, 256 threads, 8x8 microtile with
// packed f32x2 accumulators (rows paired). Register-prefetch pipelining of the
// next K-tile's global loads. Cols split {tx*4, 64+tx*4} for <=2-way conflict.
// ============================================================================
__global__ __launch_bounds__(256) void gemm_kernel(
    const float* __restrict__ W, const float* __restrict__ X,
    const float* __restrict__ bias, float* __restrict__ outp,
    int K, const float* __restrict__ mm)
{
    __shared__ float Ws[16][128];
    __shared__ float Xs[16][128];

    const int n0 = blockIdx.x * 128;
    const int m0 = blockIdx.y * 128;
    const int tid = threadIdx.x;
    const int tx = tid & 15;    // cols tx*4 .. +3  and  64+tx*4 .. +3
    const int ty = tid >> 4;    // rows ty*8 .. +7

    // per-thread load coordinates (fixed across tiles)
    const int wm = tid >> 4,  wk = tid & 15;    // W: 8 rows, stride 16 in m
    const int xk = tid >> 7,  xn = tid & 127;   // X: 8 k-rows, stride 2 in k

    u64 acc2[4][8];             // [row-pair][col]: rows (ty*8+2i, ty*8+2i+1)
#pragma unroll
    for (int i = 0; i < 4; i++)
#pragma unroll
        for (int j = 0; j < 8; j++) acc2[i][j] = 0ull;

    float wreg[8], xreg[8];

    // prefetch tile 0
#pragma unroll
    for (int i = 0; i < 8; i++)
        wreg[i] = W[(size_t)(m0 + wm + 16 * i) * K + wk];
#pragma unroll
    for (int i = 0; i < 8; i++)
        xreg[i] = X[(size_t)(xk + 2 * i) * LSEQ + n0 + xn];

    for (int k0 = 0; k0 < K; k0 += 16) {
        // commit prefetched tile to smem
#pragma unroll
        for (int i = 0; i < 8; i++) Ws[wk][wm + 16 * i] = wreg[i];
#pragma unroll
        for (int i = 0; i < 8; i++) Xs[xk + 2 * i][xn] = xreg[i];
        __syncthreads();

        // prefetch next tile while computing this one
        if (k0 + 16 < K) {
#pragma unroll
            for (int i = 0; i < 8; i++)
                wreg[i] = W[(size_t)(m0 + wm + 16 * i) * K + k0 + 16 + wk];
#pragma unroll
            for (int i = 0; i < 8; i++)
                xreg[i] = X[(size_t)(k0 + 16 + xk + 2 * i) * LSEQ + n0 + xn];
        }

#pragma unroll
        for (int kk = 0; kk < 16; kk++) {
            float4 a0 = *(const float4*)&Ws[kk][ty * 8];
            float4 a1 = *(const float4*)&Ws[kk][ty * 8 + 4];
            u64 ra[4] = {pk2(a0.x, a0.y), pk2(a0.z, a0.w),
                         pk2(a1.x, a1.y), pk2(a1.z, a1.w)};
            float4 b0 = *(const float4*)&Xs[kk][tx * 4];
            float4 b1 = *(const float4*)&Xs[kk][64 + tx * 4];
            u64 rb[8] = {dup2(b0.x), dup2(b0.y), dup2(b0.z), dup2(b0.w),
                         dup2(b1.x), dup2(b1.y), dup2(b1.z), dup2(b1.w)};
#pragma unroll
            for (int i = 0; i < 4; i++)
#pragma unroll
                for (int j = 0; j < 8; j++) fma2(acc2[i][j], ra[i], rb[j]);
        }
        __syncthreads();
    }

    // epilogue: bias, optional mask, float4 stores
    float mv[8];
#pragma unroll
    for (int j = 0; j < 4; j++) {
        mv[j]     = mm ? mm[n0 + tx * 4 + j]      : 1.f;
        mv[4 + j] = mm ? mm[n0 + 64 + tx * 4 + j] : 1.f;
    }
#pragma unroll
    for (int i = 0; i < 4; i++) {
        int r0 = m0 + ty * 8 + 2 * i;
        int r1 = r0 + 1;
        float bb0 = bias[r0], bb1 = bias[r1];
        float v0[8], v1[8];
#pragma unroll
        for (int j = 0; j < 8; j++) {
            float2 p = up2(acc2[i][j]);
            v0[j] = (p.x + bb0) * mv[j];
            v1[j] = (p.y + bb1) * mv[j];
        }
        *(float4*)&outp[(size_t)r0 * LSEQ + n0 + tx * 4]      = make_float4(v0[0], v0[1], v0[2], v0[3]);
        *(float4*)&outp[(size_t)r0 * LSEQ + n0 + 64 + tx * 4] = make_float4(v0[4], v0[5], v0[6], v0[7]);
        *(float4*)&outp[(size_t)r1 * LSEQ + n0 + tx * 4]      = make_float4(v1[0], v1[1], v1[2], v1[3]);
        *(float4*)&outp[(size_t)r1 * LSEQ + n0 + 64 + tx * 4] = make_float4(v1[4], v1[5], v1[6], v1[7]);
    }
}

// ============================================================================
// Sliding-window attention with online softmax (packed-f32x2 inner loops).
// Grid: (BLK/QT, LSEQ/BLK) = (8, 64). 256 threads.
// Each CTA: 64 queries (block n, offset q0), window cols [q0, q0+575] of the
// 1024-wide padded window, 9 chunks of 64 keys. Query r (pos n*512+q0+r)
// attends keys [pos-256, pos+255] clipped to [0,L) and mask>0.
// Output: g_att[c][pos] = relu(softmax-weighted V), relu fused.
// Softmax ignores the reference's log(fmask+1e-6) leakage (~1e-6 rel effect).
// ============================================================================
#define ATT_SMEM_FLOATS (16384 + 16896 + 4160 + 4608 + 256 + 256)
#define ATT_SMEM_BYTES  (ATT_SMEM_FLOATS * 4)

__global__ __launch_bounds__(256, 1) void att_kernel(const float* __restrict__ mask)
{
    extern __shared__ float sm[];
    float* Qs   = sm;            // [256][64]
    float* KV   = sm + 16384;    // K: stride 64, V: stride 66
    float* Ss   = sm + 33280;    // [64][65]
    float* Pt   = sm + 37440;    // [64][72]
    float* part = sm + 42048;    // [4][64]
    float* m_s  = part + 256;
    float* l_s  = m_s + 64;
    float* sc_s = l_s + 64;
    float* msk  = sc_s + 64;

    const int n  = blockIdx.y;
    const int q0 = blockIdx.x * QT;
    const int Q0 = n * BLK + q0;
    const int tid  = threadIdx.x;
    const int tx   = tid & 15;   // S-GEMM cols tx*4
    const int ty   = tid >> 4;   // S-GEMM rows ty*4
    const int cgrp = tid >> 3;   // O-GEMM channels cgrp*8..+7
    const int rgrp = tid & 7;    // O-GEMM rows rgrp*8..+7

    for (int i = tid; i < CDIM * QT; i += 256) {
        int c = i >> 6, r = i & 63;
        Qs[c * 64 + r] = g_q[(size_t)c * LSEQ + Q0 + r];
    }
    if (tid < 64) { m_s[tid] = -INFINITY; l_s[tid] = 0.f; }

    u64 acc2[8][4];              // [ci][row-pair]: rows (rgrp*8+2rp, +1)
#pragma unroll
    for (int i = 0; i < 8; i++)
#pragma unroll
        for (int j = 0; j < 4; j++) acc2[i][j] = 0ull;
    __syncthreads();

    const float escale = 0.0625f;  // 1/sqrt(256)

    for (int ch = 0; ch < 9; ch++) {
        const int c0 = q0 + ch * 64;            // window col base
        const int kbase = n * BLK - HALF + c0;  // global key pos of j=0

        // ---- load K chunk (stride 64) + mask chunk ----
        for (int i = tid; i < CDIM * 64; i += 256) {
            int c = i >> 6, j = i & 63;
            int kp = kbase + j;
            int kpc = min(max(kp, 0), LSEQ - 1);
            KV[c * 64 + j] = g_k[(size_t)c * LSEQ + kpc];
        }
        if (tid < 64) {
            int kp = kbase + tid;
            msk[tid] = (kp >= 0 && kp < LSEQ) ? mask[kp] : 0.f;
        }
        __syncthreads();

        // ---- S = scale * Q^T K (packed rows), band-masked, into Ss ----
        u64 s2[2][4];
#pragma unroll
        for (int i = 0; i < 2; i++)
#pragma unroll
            for (int j = 0; j < 4; j++) s2[i][j] = 0ull;
#pragma unroll 8
        for (int c = 0; c < CDIM; c++) {
            float4 a = *(const float4*)&Qs[c * 64 + ty * 4];
            float4 b = *(const float4*)&KV[c * 64 + tx * 4];
            u64 ra0 = pk2(a.x, a.y), ra1 = pk2(a.z, a.w);
            u64 rb[4] = {dup2(b.x), dup2(b.y), dup2(b.z), dup2(b.w)};
#pragma unroll
            for (int j = 0; j < 4; j++) {
                fma2(s2[0][j], ra0, rb[j]);
                fma2(s2[1][j], ra1, rb[j]);
            }
        }
        float s4[4][4];
#pragma unroll
        for (int j = 0; j < 4; j++) {
            float2 p0 = up2(s2[0][j]);
            float2 p1 = up2(s2[1][j]);
            s4[0][j] = p0.x; s4[1][j] = p0.y;
            s4[2][j] = p1.x; s4[3][j] = p1.y;
        }
#pragma unroll
        for (int i = 0; i < 4; i++) {
            int r = ty * 4 + i;
            int arow = q0 + r;
#pragma unroll
            for (int j = 0; j < 4; j++) {
                int jj = tx * 4 + j;
                int wcol = c0 + jj;
                bool valid = (wcol >= arow) && (wcol < arow + BLK) && (msk[jj] > 0.f);
                Ss[r * 65 + jj] = valid ? s4[i][j] * escale : -INFINITY;
            }
        }
        __syncthreads();

        // ---- load V chunk (stride 66, overwrites K) + row-max partials ----
        for (int i = tid; i < CDIM * 64; i += 256) {
            int c = i >> 6, j = i & 63;
            int kp = kbase + j;
            int kpc = min(max(kp, 0), LSEQ - 1);
            KV[c * 66 + j] = g_v[(size_t)c * LSEQ + kpc];
        }
        {
            int r = tid & 63, qq = tid >> 6;
            float mx = -INFINITY;
#pragma unroll
            for (int k = 0; k < 16; k++)
                mx = fmaxf(mx, Ss[r * 65 + qq + 4 * k]);
            part[qq * 64 + r] = mx;
        }
        __syncthreads();

        // ---- online softmax stats update ----
        if (tid < 64) {
            float m_old = m_s[tid];
            float mx = fmaxf(fmaxf(part[tid], part[64 + tid]),
                             fmaxf(part[128 + tid], part[192 + tid]));
            float m_new = fmaxf(m_old, mx);
            float sc = (m_new > -1e30f) ? __expf(m_old - m_new) : 1.0f;
            m_s[tid] = m_new;
            sc_s[tid] = sc;
            l_s[tid] *= sc;
        }
        __syncthreads();

        // ---- P = exp(S - m), transposed into Pt[j][r], row-sum partials ----
        {
            int r = tid & 63, qq = tid >> 6;
            float mrow = m_s[r];
            float ps = 0.f;
#pragma unroll
            for (int k = 0; k < 16; k++) {
                int j = qq + 4 * k;
                float s = Ss[r * 65 + j];
                float p = (s > -1e30f) ? __expf(s - mrow) : 0.f;
                Pt[j * 72 + r] = p;
                ps += p;
            }
            part[qq * 64 + r] = ps;
        }
        __syncthreads();

        if (tid < 64)
            l_s[tid] += part[tid] + part[64 + tid] + part[128 + tid] + part[192 + tid];

        // ---- O accumulate: rescale then acc += V[c][j] * P[j][r] (packed) ----
#pragma unroll
        for (int rp = 0; rp < 4; rp++) {
            u64 sc = pk2(sc_s[rgrp * 8 + 2 * rp], sc_s[rgrp * 8 + 2 * rp + 1]);
#pragma unroll
            for (int ci = 0; ci < 8; ci++) mul2(acc2[ci][rp], sc);
        }
#pragma unroll 2
        for (int j = 0; j < 64; j++) {
            float4 p0 = *(const float4*)&Pt[j * 72 + rgrp * 8];
            float4 p1 = *(const float4*)&Pt[j * 72 + rgrp * 8 + 4];
            u64 rp[4] = {pk2(p0.x, p0.y), pk2(p0.z, p0.w),
                         pk2(p1.x, p1.y), pk2(p1.z, p1.w)};
#pragma unroll
            for (int ci = 0; ci < 8; ci++) {
                u64 vv = dup2(KV[(cgrp * 8 + ci) * 66 + j]);
#pragma unroll
                for (int r4 = 0; r4 < 4; r4++) fma2(acc2[ci][r4], vv, rp[r4]);
            }
        }
        __syncthreads();
    }

    // ---- epilogue: normalize, relu, store ----
#pragma unroll
    for (int rp = 0; rp < 4; rp++) {
        int r0 = rgrp * 8 + 2 * rp;
        int r1 = r0 + 1;
        float l0 = l_s[r0], l1 = l_s[r1];
        float inv0 = (l0 > 0.f) ? 1.0f / l0 : 0.f;
        float inv1 = (l1 > 0.f) ? 1.0f / l1 : 0.f;
#pragma unroll
        for (int ci = 0; ci < 8; ci++) {
            int c = cgrp * 8 + ci;
            float2 v = up2(acc2[ci][rp]);
            g_att[(size_t)c * LSEQ + Q0 + r0] = fmaxf(v.x * inv0, 0.f);
            g_att[(size_t)c * LSEQ + Q0 + r1] = fmaxf(v.y * inv1, 0.f);
        }
    }
}

// ============================================================================
extern "C" void kernel_launch(void* const* d_in, const int* in_sizes, int n_in,
                              void* d_out, int out_size)
{
    (void)in_sizes; (void)n_in; (void)out_size;
    const float* x1   = (const float*)d_in[0];
    // d_in[1] = x2 (unused by reference)
    const float* mask = (const float*)d_in[2];
    const float* Wq = (const float*)d_in[3];
    const float* bq = (const float*)d_in[4];
    const float* Wk = (const float*)d_in[5];
    const float* bk = (const float*)d_in[6];
    const float* Wv = (const float*)d_in[7];
    const float* bv = (const float*)d_in[8];
    const float* Wo = (const float*)d_in[9];
    const float* bo = (const float*)d_in[10];
    float* out = (float*)d_out;

    float *pq, *pk, *pv, *patt;
    cudaGetSymbolAddress((void**)&pq,  g_q);
    cudaGetSymbolAddress((void**)&pk,  g_k);
    cudaGetSymbolAddress((void**)&pv,  g_v);
    cudaGetSymbolAddress((void**)&patt, g_att);

    cudaFuncSetAttribute(att_kernel,
                         cudaFuncAttributeMaxDynamicSharedMemorySize, ATT_SMEM_BYTES);

    // QKV projections: M=256, K=512
    dim3 g1(LSEQ / 128, CDIM / 128);
    gemm_kernel<<<g1, 256>>>(Wq, x1, bq, pq, QDIM, nullptr);
    gemm_kernel<<<g1, 256>>>(Wk, x1, bk, pk, QDIM, nullptr);
    gemm_kernel<<<g1, 256>>>(Wv, x1, bv, pv, QDIM, nullptr);

    // Sliding-window attention (+ relu), writes g_att
    dim3 ga(BLK / QT, LSEQ / BLK);
    att_kernel<<<ga, 256, ATT_SMEM_BYTES>>>(mask);

    // Output projection: M=512, K=256, fused bias + final mask multiply
    dim3 g2(LSEQ / 128, QDIM / 128);
    gemm_kernel<<<g2, 256>>>(Wo, patt, bo, out, CDIM, mask);
}